// round 8
// baseline (speedup 1.0000x reference)
#include <cuda_runtime.h>
#include <cuda_fp16.h>
#include <cstdint>

// Problem constants
#define NPIX   65536
#define BATCH  2
#define MROWS  524288
#define KW1    208          // X row length in packed words (416 halves)

// Static scratch. Row-major packed half2: row m has KW contiguous words.
// g_B1: X(208w) / act2(256w) / act4-fp32(128f)   g_A: act1(512w) / act3(128w)
__device__ uint32_t g_B1[256u * 524288u];   // 536 MB
__device__ uint32_t g_A[512u * 524288u];    // 1073 MB
__device__ uint32_t g_W[557056];            // packed fp16 weights, row-major [No][KW]

// ---------------- helpers ----------------
__device__ __forceinline__ void mma_f16(float c[4], const uint32_t a[4],
                                        uint32_t b0, uint32_t b1) {
    asm volatile(
        "mma.sync.aligned.m16n8k16.row.col.f32.f16.f16.f32 "
        "{%0,%1,%2,%3}, {%4,%5,%6,%7}, {%8,%9}, {%0,%1,%2,%3};\n"
        : "+f"(c[0]), "+f"(c[1]), "+f"(c[2]), "+f"(c[3])
        : "r"(a[0]), "r"(a[1]), "r"(a[2]), "r"(a[3]), "r"(b0), "r"(b1));
}
__device__ __forceinline__ void ldsm4(uint32_t r[4], uint32_t addr) {
    asm volatile("ldmatrix.sync.aligned.m8n8.x4.shared.b16 {%0,%1,%2,%3}, [%4];"
                 : "=r"(r[0]), "=r"(r[1]), "=r"(r[2]), "=r"(r[3]) : "r"(addr));
}
__device__ __forceinline__ uint32_t s2u(const void* p) {
    uint32_t a;
    asm("{ .reg .u64 t; cvta.to.shared.u64 t, %1; cvt.u32.u64 %0, t; }" : "=r"(a) : "l"(p));
    return a;
}
__device__ __forceinline__ void cpasync16(uint32_t smem, const void* gmem) {
    asm volatile("cp.async.cg.shared.global [%0], [%1], 16;\n" :: "r"(smem), "l"(gmem));
}
__device__ __forceinline__ uint32_t packh2(float a, float b) {
    __half2 h = __floats2half2_rn(a, b);
    return *(uint32_t*)&h;
}

// ---------------- weight prep: transpose to [No][KW] packed ----------------
__global__ void k_prep(const float* __restrict__ w, uint32_t* __restrict__ dst,
                       int Ksrc, int KW, int No) {
    int i = blockIdx.x * 256 + threadIdx.x;
    if (i >= KW * No) return;
    int j = i / KW;
    int kk = i - j * KW;
    int k0 = 2 * kk, k1 = 2 * kk + 1;
    float v0 = (k0 < Ksrc) ? w[(size_t)k0 * No + j] : 0.f;
    float v1 = (k1 < Ksrc) ? w[(size_t)k1 * No + j] : 0.f;
    dst[(size_t)j * KW + kk] = packh2(v0, v1);
}

// ---------------- build X row-major [M][208] packed ----------------
__global__ void k_build(const float* __restrict__ feat, const float* __restrict__ coord,
                        const float* __restrict__ hr, const float* __restrict__ lr,
                        uint32_t* __restrict__ X) {
    __shared__ uint32_t sm[32][208];
    __shared__ int   s_lr[32], s_hr[32];
    __shared__ float s_fL[32], s_fH[32], s_r0[32], s_r1[32];

    int tid = threadIdx.x;
    int b = blockIdx.y, s = blockIdx.z;
    float vx = (s & 2) ? 1.f : -1.f;
    float vy = (s & 1) ? 1.f : -1.f;

    if (tid < 32) {
        int n = blockIdx.x * 32 + tid;
        float gy = coord[((size_t)b * NPIX + n) * 2 + 0];
        float gx = coord[((size_t)b * NPIX + n) * 2 + 1];
        int iyH = (int)floorf((gy + 1.f) * 128.f);
        int ixH = (int)floorf((gx + 1.f) * 128.f);
        bool vH = (iyH >= 0) && (iyH < 256) && (ixH >= 0) && (ixH < 256);
        int iyHc = min(max(iyH, 0), 255), ixHc = min(max(ixH, 0), 255);
        float cy = gy + vx * (1.f / 64.f);
        float cx = gx + vy * (1.f / 64.f);
        int iyL = (int)floorf((cy + 1.f) * 32.f);
        int ixL = (int)floorf((cx + 1.f) * 32.f);
        bool vL = (iyL >= 0) && (iyL < 64) && (ixL >= 0) && (ixL < 64);
        int iyLc = min(max(iyL, 0), 63), ixLc = min(max(ixL, 0), 63);
        float qcy = vL ? (-1.f + 0.015625f + 0.03125f * (float)iyLc) : 0.f;
        float qcx = vL ? (-1.f + 0.015625f + 0.03125f * (float)ixLc) : 0.f;
        s_hr[tid] = iyHc * 256 + ixHc;
        s_lr[tid] = iyLc * 64 + ixLc;
        s_fH[tid] = vH ? 1.f : 0.f;
        s_fL[tid] = vL ? 1.f : 0.f;
        s_r0[tid] = (gy - qcy) * 64.f;
        s_r1[tid] = (gx - qcx) * 64.f;
    }
    __syncthreads();

    int p = tid >> 3, t = tid & 7;
    {
        float fL = s_fL[p], fH = s_fH[p];
        size_t hrb = ((size_t)b * 128) * 65536 + s_hr[p];
        size_t lrb = ((size_t)b * 128) * 4096 + s_lr[p];
        for (int w = t; w < 208; w += 8) {
            float v0, v1;
            if (w < 64) {
                int c = 2 * w;
                v0 = fL * feat[lrb + (size_t)c * 4096];
                v1 = fL * feat[lrb + (size_t)(c + 1) * 4096];
            } else if (w < 128) {
                int c = 2 * (w - 64);
                v0 = fH * hr[hrb + (size_t)c * 65536];
                v1 = fH * hr[hrb + (size_t)(c + 1) * 65536];
            } else if (w < 192) {
                int c = 2 * (w - 128);
                v0 = fH * hr[hrb + (size_t)c * 65536] - fL * lr[lrb + (size_t)c * 4096];
                v1 = fH * hr[hrb + (size_t)(c + 1) * 65536] - fL * lr[lrb + (size_t)(c + 1) * 4096];
            } else if (w == 192) {
                v0 = s_r0[p]; v1 = s_r1[p];
            } else {
                v0 = 0.f; v1 = 0.f;
            }
            sm[p][w] = packh2(v0, v1);
        }
    }
    __syncthreads();

    size_t r0 = ((size_t)(s * BATCH + b) << 16) + (size_t)blockIdx.x * 32;
    for (int idx = tid; idx < 32 * 52; idx += 256) {
        int r = idx / 52, q = idx - r * 52;
        uint4 v = *(uint4*)&sm[r][q * 4];
        *(uint4*)&X[(r0 + r) * KW1 + q * 4] = v;
    }
}

// ---------------- fp16 GEMM (ldmatrix path) ----------------
// out[m][n] = relu(sum_k in[m][k] * W[n][k] + bias[n]).
// SMEM tiles: 128 rows x 16 words (64B rows, 4x16B units, XOR swizzle).
union SmemU {
    struct { uint32_t A[2][2048]; uint32_t B[2][2048]; } p;  // 32KB pipeline
    uint32_t stage[128 * 68];                                // 34.8KB epilogue
};

__global__ void __launch_bounds__(128, 2)
k_gemm(const uint32_t* __restrict__ in, const uint32_t* __restrict__ W,
       const float* __restrict__ bias, uint32_t* __restrict__ out16,
       float* __restrict__ out32, int KW, int NoW, int pack16) {
    __shared__ SmemU su;
    __shared__ float bias_s[128];

    int n0 = blockIdx.x * 128;
    size_t m0 = (size_t)blockIdx.y * 128;
    int tid = threadIdx.x;
    int wrp = tid >> 5, lane = tid & 31;
    int gid = lane >> 2, ctid = lane & 3;
    int warp_m = (wrp & 1) * 64;
    int warp_n = (wrp >> 1) * 64;

    bias_s[tid] = bias[n0 + tid];

    uint32_t sbA = s2u(su.p.A[0]);
    uint32_t sbB = s2u(su.p.B[0]);

    // ldmatrix address offsets (bytes) per k16 slice s in {0,1}
    int mA = warp_m + (lane & 7) + (lane & 8);
    int uA = (lane >> 4) & 1;
    int nB = warp_n + (lane & 7) + ((lane >> 4) << 3);
    int uB = (lane >> 3) & 1;
    uint32_t aoff[2], boff[2];
#pragma unroll
    for (int s = 0; s < 2; s++) {
        aoff[s] = (uint32_t)(mA * 64 + (((2 * s + uA) ^ ((mA >> 1) & 3)) * 16));
        boff[s] = (uint32_t)(nB * 64 + (((2 * s + uB) ^ ((nB >> 1) & 3)) * 16));
    }

    float acc[4][8][4];
#pragma unroll
    for (int a = 0; a < 4; a++)
#pragma unroll
        for (int bq = 0; bq < 8; bq++)
#pragma unroll
            for (int c = 0; c < 4; c++) acc[a][bq][c] = 0.f;

    int KT = KW >> 4;

    // prologue: chunk 0 -> buf 0
#pragma unroll
    for (int i = tid; i < 512; i += 128) {
        int m = i >> 2, u = i & 3;
        uint32_t sw = (uint32_t)(m * 64 + ((u ^ ((m >> 1) & 3)) * 16));
        cpasync16(sbA + sw, in + (m0 + m) * (size_t)KW + 4 * u);
        cpasync16(sbB + sw, W + (size_t)(n0 + m) * KW + 4 * u);
    }
    asm volatile("cp.async.commit_group;\n" ::);

    for (int kt = 0; kt < KT; kt++) {
        int cur = kt & 1;
        if (kt + 1 < KT) {
            int kw0 = (kt + 1) * 16;
            int nxt = cur ^ 1;
#pragma unroll
            for (int i = tid; i < 512; i += 128) {
                int m = i >> 2, u = i & 3;
                uint32_t sw = (uint32_t)(m * 64 + ((u ^ ((m >> 1) & 3)) * 16));
                cpasync16(sbA + nxt * 8192 + sw, in + (m0 + m) * (size_t)KW + kw0 + 4 * u);
                cpasync16(sbB + nxt * 8192 + sw, W + (size_t)(n0 + m) * KW + kw0 + 4 * u);
            }
            asm volatile("cp.async.commit_group;\n" ::);
            asm volatile("cp.async.wait_group 1;\n" ::);
        } else {
            asm volatile("cp.async.wait_group 0;\n" ::);
        }
        __syncthreads();

        uint32_t Ab = sbA + cur * 8192;
        uint32_t Bb = sbB + cur * 8192;
#pragma unroll
        for (int s = 0; s < 2; s++) {
            uint32_t afr[4][4], bfr[4][4];
#pragma unroll
            for (int mt = 0; mt < 4; mt++) ldsm4(afr[mt], Ab + aoff[s] + mt * 1024);
#pragma unroll
            for (int pq = 0; pq < 4; pq++) ldsm4(bfr[pq], Bb + boff[s] + pq * 1024);
#pragma unroll
            for (int mt = 0; mt < 4; mt++)
#pragma unroll
                for (int pq = 0; pq < 4; pq++) {
                    mma_f16(acc[mt][2 * pq],     afr[mt], bfr[pq][0], bfr[pq][1]);
                    mma_f16(acc[mt][2 * pq + 1], afr[mt], bfr[pq][2], bfr[pq][3]);
                }
        }
        __syncthreads();
    }

    // epilogue
    if (pack16) {
        // stage packed words in smem [128][68], then row-contiguous uint4 stores
#pragma unroll
        for (int mt = 0; mt < 4; mt++) {
            int m = warp_m + mt * 16 + gid;
#pragma unroll
            for (int nt = 0; nt < 8; nt++) {
                int j = warp_n + nt * 8 + 2 * ctid;
                float v0 = fmaxf(acc[mt][nt][0] + bias_s[j], 0.f);
                float v1 = fmaxf(acc[mt][nt][1] + bias_s[j + 1], 0.f);
                float v2 = fmaxf(acc[mt][nt][2] + bias_s[j], 0.f);
                float v3 = fmaxf(acc[mt][nt][3] + bias_s[j + 1], 0.f);
                int wc = (j >> 1);
                su.stage[m * 68 + wc]       = packh2(v0, v1);
                su.stage[(m + 8) * 68 + wc] = packh2(v2, v3);
            }
        }
        __syncthreads();
        int wbase = n0 >> 1;
#pragma unroll
        for (int idx = tid; idx < 128 * 16; idx += 128) {
            int r = idx >> 4, q = idx & 15;
            uint4 v = *(uint4*)&su.stage[r * 68 + q * 4];
            *(uint4*)&out16[(m0 + r) * (size_t)NoW + wbase + q * 4] = v;
        }
    } else {
        // L4: fp32 row-major [M][128], direct float2 stores (32B sectors full)
#pragma unroll
        for (int mt = 0; mt < 4; mt++) {
            size_t m = m0 + (size_t)(warp_m + mt * 16 + gid);
#pragma unroll
            for (int nt = 0; nt < 8; nt++) {
                int j = warp_n + nt * 8 + 2 * ctid;
                float v0 = fmaxf(acc[mt][nt][0] + bias_s[j], 0.f);
                float v1 = fmaxf(acc[mt][nt][1] + bias_s[j + 1], 0.f);
                float v2 = fmaxf(acc[mt][nt][2] + bias_s[j], 0.f);
                float v3 = fmaxf(acc[mt][nt][3] + bias_s[j + 1], 0.f);
                *(float2*)&out32[m * 128 + n0 + j]       = make_float2(v0, v1);
                *(float2*)&out32[(m + 8) * 128 + n0 + j] = make_float2(v2, v3);
            }
        }
    }
}

// ---------------- layer 5 + softmax combine (act4 fp32 row-major [M][128]) ----------------
__global__ void k_combine(const float* __restrict__ act,
                          const float* __restrict__ w5, const float* __restrict__ b5,
                          float* __restrict__ out) {
    __shared__ float2 ws[128];
    int tid = threadIdx.x;
    if (tid < 128) ws[tid] = make_float2(w5[2 * tid], w5[2 * tid + 1]);
    __syncthreads();

    int wid = tid >> 5, lane = tid & 31;
    int pg = blockIdx.x * 8 + wid;
    int b = pg >> 16, n = pg & 65535;

    float p0[4], p1[4];
#pragma unroll
    for (int s = 0; s < 4; s++) {
        size_t r = ((size_t)(s * BATCH + b) << 16) + (size_t)n;
        const float* row = act + r * 128;
        float4 v = *(const float4*)&row[lane * 4];
        float2 w0 = ws[4 * lane], w1 = ws[4 * lane + 1];
        float2 w2 = ws[4 * lane + 2], w3 = ws[4 * lane + 3];
        float a0 = v.x * w0.x + v.y * w1.x + v.z * w2.x + v.w * w3.x;
        float a1 = v.x * w0.y + v.y * w1.y + v.z * w2.y + v.w * w3.y;
#pragma unroll
        for (int o = 16; o > 0; o >>= 1) {
            a0 += __shfl_xor_sync(0xFFFFFFFF, a0, o);
            a1 += __shfl_xor_sync(0xFFFFFFFF, a1, o);
        }
        p0[s] = a0 + b5[0];
        p1[s] = a1 + b5[1];
    }
    if (lane == 0) {
        float mx = fmaxf(fmaxf(p1[0], p1[1]), fmaxf(p1[2], p1[3]));
        float e0 = expf(p1[0] - mx), e1 = expf(p1[1] - mx);
        float e2 = expf(p1[2] - mx), e3 = expf(p1[3] - mx);
        float sum = e0 + e1 + e2 + e3;
        out[(size_t)b * NPIX + n] = (p0[0] * e0 + p0[1] * e1 + p0[2] * e2 + p0[3] * e3) / sum;
    }
}

// ---------------- launch ----------------
extern "C" void kernel_launch(void* const* d_in, const int* in_sizes, int n_in,
                              void* d_out, int out_size) {
    const float* feat  = (const float*)d_in[0];
    const float* coord = (const float*)d_in[1];
    const float* hr    = (const float*)d_in[2];
    const float* lr    = (const float*)d_in[3];
    const float* w1 = (const float*)d_in[4];
    const float* b1 = (const float*)d_in[5];
    const float* w2 = (const float*)d_in[6];
    const float* b2 = (const float*)d_in[7];
    const float* w3 = (const float*)d_in[8];
    const float* b3 = (const float*)d_in[9];
    const float* w4 = (const float*)d_in[10];
    const float* b4 = (const float*)d_in[11];
    const float* w5 = (const float*)d_in[12];
    const float* b5 = (const float*)d_in[13];

    uint32_t *B1, *A, *Wb;
    cudaGetSymbolAddress((void**)&B1, g_B1);
    cudaGetSymbolAddress((void**)&A,  g_A);
    cudaGetSymbolAddress((void**)&Wb, g_W);

    uint32_t* W1 = Wb;                        // [1024][208]
    uint32_t* W2 = W1 + 1024 * 208;           // [512][512]
    uint32_t* W3 = W2 + 512 * 512;            // [256][256]
    uint32_t* W4 = W3 + 256 * 256;            // [128][128]

    k_prep<<<(1024 * 208 + 255) / 256, 256>>>(w1, W1, 386, 208, 1024);
    k_prep<<<(512 * 512 + 255) / 256, 256>>>(w2, W2, 1024, 512, 512);
    k_prep<<<(256 * 256 + 255) / 256, 256>>>(w3, W3, 512, 256, 256);
    k_prep<<<(128 * 128 + 255) / 256, 256>>>(w4, W4, 256, 128, 128);

    k_build<<<dim3(2048, 2, 4), 256>>>(feat, coord, hr, lr, B1);

    // L1: X[M][208] -> act1[M][512] in A
    k_gemm<<<dim3(8, 4096), 128>>>(B1, W1, b1, A, nullptr, 208, 512, 1);
    // L2: act1 -> act2[M][256] in B1
    k_gemm<<<dim3(4, 4096), 128>>>(A, W2, b2, B1, nullptr, 512, 256, 1);
    // L3: act2 -> act3[M][128] in A
    k_gemm<<<dim3(2, 4096), 128>>>(B1, W3, b3, A, nullptr, 256, 128, 1);
    // L4: act3 -> act4 fp32 [M][128] in B1
    k_gemm<<<dim3(1, 4096), 128>>>(A, W4, b4, nullptr, (float*)B1, 128, 0, 0);

    k_combine<<<BATCH * NPIX / 8, 256>>>((const float*)B1, w5, b5, (float*)d_out);
}

// round 9
// speedup vs baseline: 1.4895x; 1.4895x over previous
#include <cuda_runtime.h>
#include <cuda_fp16.h>
#include <cstdint>

// Problem constants
#define NPIX   65536
#define BATCH  2
#define MROWS  524288
#define PROWS  131072       // B * NPIX (pixel-GEMM rows)

// Static scratch. Row-major packed half2.
__device__ uint32_t g_A[512u * 524288u];    // act1 [M][512w] / act3 [M][128w]
__device__ uint32_t g_B1[256u * 524288u];   // act2 [M][256w] / act4 fp32 [M][128f]
__device__ uint32_t g_Gp[131072u * 80u];    // pixel-GEMM input [PROWS][80w]
__device__ uint32_t g_Gc[8320u * 144u];     // cell-GEMM input [8320][144w]
__device__ float    g_C[8320u * 1024u];     // cell table fp32 [8320][1024]
__device__ int      g_idx[131072u * 4u];    // per-(pixel,shift) cell row
__device__ uint32_t g_W[600000];            // packed fp16 weights

// ---------------- helpers ----------------
__device__ __forceinline__ void mma_f16(float c[4], const uint32_t a[4],
                                        uint32_t b0, uint32_t b1) {
    asm volatile(
        "mma.sync.aligned.m16n8k16.row.col.f32.f16.f16.f32 "
        "{%0,%1,%2,%3}, {%4,%5,%6,%7}, {%8,%9}, {%0,%1,%2,%3};\n"
        : "+f"(c[0]), "+f"(c[1]), "+f"(c[2]), "+f"(c[3])
        : "r"(a[0]), "r"(a[1]), "r"(a[2]), "r"(a[3]), "r"(b0), "r"(b1));
}
__device__ __forceinline__ void ldsm4(uint32_t r[4], uint32_t addr) {
    asm volatile("ldmatrix.sync.aligned.m8n8.x4.shared.b16 {%0,%1,%2,%3}, [%4];"
                 : "=r"(r[0]), "=r"(r[1]), "=r"(r[2]), "=r"(r[3]) : "r"(addr));
}
__device__ __forceinline__ uint32_t s2u(const void* p) {
    uint32_t a;
    asm("{ .reg .u64 t; cvta.to.shared.u64 t, %1; cvt.u32.u64 %0, t; }" : "=r"(a) : "l"(p));
    return a;
}
__device__ __forceinline__ void cpasync16(uint32_t smem, const void* gmem) {
    asm volatile("cp.async.cg.shared.global [%0], [%1], 16;\n" :: "r"(smem), "l"(gmem));
}
__device__ __forceinline__ uint32_t packh2(float a, float b) {
    __half2 h = __floats2half2_rn(a, b);
    return *(uint32_t*)&h;
}

// ---------------- weight preps ----------------
// generic: dst[j][kk] from w[k][No] (transpose + pack + zero pad)
__global__ void k_prep(const float* __restrict__ w, uint32_t* __restrict__ dst,
                       int Ksrc, int KW, int No) {
    int i = blockIdx.x * 256 + threadIdx.x;
    if (i >= KW * No) return;
    int j = i / KW;
    int kk = i - j * KW;
    int k0 = 2 * kk, k1 = 2 * kk + 1;
    float v0 = (k0 < Ksrc) ? w[(size_t)k0 * No + j] : 0.f;
    float v1 = (k1 < Ksrc) ? w[(size_t)k1 * No + j] : 0.f;
    dst[(size_t)j * KW + kk] = packh2(v0, v1);
}
// pixel weights: Wg[j][80w]: k<128 -> W1[128+k]+W1[256+k]; k=128,129 -> W1[384],W1[385]
__global__ void k_prepWg(const float* __restrict__ w1, uint32_t* __restrict__ dst) {
    int i = blockIdx.x * 256 + threadIdx.x;
    if (i >= 1024 * 80) return;
    int j = i / 80, kk = i - j * 80;
    float v0 = 0.f, v1 = 0.f;
    if (kk < 64) {
        int c = 2 * kk;
        v0 = w1[(size_t)(128 + c) * 1024 + j] + w1[(size_t)(256 + c) * 1024 + j];
        v1 = w1[(size_t)(129 + c) * 1024 + j] + w1[(size_t)(257 + c) * 1024 + j];
    } else if (kk == 64) {
        v0 = w1[(size_t)384 * 1024 + j];
        v1 = w1[(size_t)385 * 1024 + j];
    }
    dst[(size_t)j * 80 + kk] = packh2(v0, v1);
}
// cell weights: Wc[j][144w]: k<128 -> W1[k]; 128..255 -> -W1[256+(k-128)]; 256,257 -> W1[384],W1[385]
__global__ void k_prepWc(const float* __restrict__ w1, uint32_t* __restrict__ dst) {
    int i = blockIdx.x * 256 + threadIdx.x;
    if (i >= 1024 * 144) return;
    int j = i / 144, kk = i - j * 144;
    float v0 = 0.f, v1 = 0.f;
    if (kk < 64) {
        int c = 2 * kk;
        v0 = w1[(size_t)c * 1024 + j];
        v1 = w1[(size_t)(c + 1) * 1024 + j];
    } else if (kk < 128) {
        int c = 2 * (kk - 64);
        v0 = -w1[(size_t)(256 + c) * 1024 + j];
        v1 = -w1[(size_t)(257 + c) * 1024 + j];
    } else if (kk == 128) {
        v0 = w1[(size_t)384 * 1024 + j];
        v1 = w1[(size_t)385 * 1024 + j];
    }
    dst[(size_t)j * 144 + kk] = packh2(v0, v1);
}

// ---------------- build pixel input Gp [PROWS][80w] + idx4 ----------------
__global__ void k_buildGp(const float* __restrict__ hr, const float* __restrict__ coord,
                          uint32_t* __restrict__ Gp, int* __restrict__ idx4) {
    __shared__ uint32_t sm[32][80];
    __shared__ int s_hi[32];
    __shared__ float s_fH[32];
    __shared__ uint32_t s_cw[32];

    int tid = threadIdx.x;
    if (tid < 32) {
        int gp = blockIdx.x * 32 + tid;
        int b = gp >> 16, n = gp & 65535;
        float gy = coord[((size_t)b * NPIX + n) * 2 + 0];
        float gx = coord[((size_t)b * NPIX + n) * 2 + 1];
        int iyH = (int)floorf((gy + 1.f) * 128.f);
        int ixH = (int)floorf((gx + 1.f) * 128.f);
        bool vH = (iyH >= 0) && (iyH < 256) && (ixH >= 0) && (ixH < 256);
        int iyHc = min(max(iyH, 0), 255), ixHc = min(max(ixH, 0), 255);
        s_hi[tid] = iyHc * 256 + ixHc;
        s_fH[tid] = vH ? 1.f : 0.f;
        s_cw[tid] = packh2(gy * 64.f, gx * 64.f);   // exact in fp16
#pragma unroll
        for (int s = 0; s < 4; s++) {
            float vx = (s & 2) ? 1.f : -1.f;
            float vy = (s & 1) ? 1.f : -1.f;
            float cy = gy + vx * (1.f / 64.f);
            float cx = gx + vy * (1.f / 64.f);
            int iyL = (int)floorf((cy + 1.f) * 32.f);
            int ixL = (int)floorf((cx + 1.f) * 32.f);
            bool vL = (iyL >= 0) && (iyL < 64) && (ixL >= 0) && (ixL < 64);
            idx4[(size_t)gp * 4 + s] = vL ? (b * 4096 + iyL * 64 + ixL) : 8192;
        }
    }
    __syncthreads();

    int p = tid >> 3, t = tid & 7;
    {
        int gp = blockIdx.x * 32 + p;
        int b = gp >> 16;
        float fH = s_fH[p];
        size_t hrb = ((size_t)b * 128) * 65536 + s_hi[p];
        for (int w = t; w < 80; w += 8) {
            uint32_t v;
            if (w < 64) {
                int c = 2 * w;
                v = packh2(fH * hr[hrb + (size_t)c * 65536],
                           fH * hr[hrb + (size_t)(c + 1) * 65536]);
            } else if (w == 64) {
                v = s_cw[p];
            } else {
                v = 0u;
            }
            sm[p][w] = v;
        }
    }
    __syncthreads();

    size_t r0 = (size_t)blockIdx.x * 32;
    for (int idx = tid; idx < 32 * 20; idx += 256) {
        int r = idx / 20, q = idx - r * 20;
        uint4 v = *(uint4*)&sm[r][q * 4];
        *(uint4*)&Gp[(r0 + r) * 80 + q * 4] = v;
    }
}

// ---------------- build cell input Gc [8320][144w] ----------------
__global__ void k_buildGc(const float* __restrict__ feat, const float* __restrict__ lr,
                          uint32_t* __restrict__ Gc) {
    int i = blockIdx.x * 256 + threadIdx.x;
    if (i >= 8320 * 144) return;
    int row = i / 144, w = i - row * 144;
    uint32_t v = 0u;
    if (row < 8192) {
        int b = row >> 12, cell = row & 4095;
        int iy = cell >> 6, ix = cell & 63;
        size_t li = (size_t)b * 128 * 4096 + iy * 64 + ix;
        if (w < 64) {
            int c = 2 * w;
            v = packh2(feat[li + (size_t)c * 4096], feat[li + (size_t)(c + 1) * 4096]);
        } else if (w < 128) {
            int c = 2 * (w - 64);
            v = packh2(lr[li + (size_t)c * 4096], lr[li + (size_t)(c + 1) * 4096]);
        } else if (w == 128) {
            // -qc*64: qcy*64 = 2*iy - 63 (exact)
            v = packh2((float)(63 - 2 * iy), (float)(63 - 2 * ix));
        }
    }
    Gc[(size_t)row * 144 + w] = v;
}

// ---------------- fp16 GEMM (ldmatrix, 128x128 CTA, 4 warps 64x64) ----------------
union SmemU {
    struct { uint32_t A[2][2048]; uint32_t B[2][2048]; } p;  // 32KB pipeline
    uint32_t stage[128 * 68];                                // 34.8KB epilogue
};

#define GEMM_PRO_MAIN(KWv)                                                             \
    uint32_t sbA = s2u(su.p.A[0]);                                                     \
    uint32_t sbB = s2u(su.p.B[0]);                                                     \
    int mA = warp_m + (lane & 7) + (lane & 8);                                         \
    int uA = (lane >> 4) & 1;                                                          \
    int nB = warp_n + (lane & 7) + ((lane >> 4) << 3);                                 \
    int uB = (lane >> 3) & 1;                                                          \
    uint32_t aoff[2], boff[2];                                                         \
    _Pragma("unroll")                                                                  \
    for (int s = 0; s < 2; s++) {                                                      \
        aoff[s] = (uint32_t)(mA * 64 + (((2 * s + uA) ^ ((mA >> 1) & 3)) * 16));       \
        boff[s] = (uint32_t)(nB * 64 + (((2 * s + uB) ^ ((nB >> 1) & 3)) * 16));       \
    }                                                                                  \
    float acc[4][8][4];                                                                \
    _Pragma("unroll")                                                                  \
    for (int a = 0; a < 4; a++)                                                        \
        _Pragma("unroll")                                                              \
        for (int bq = 0; bq < 8; bq++)                                                 \
            _Pragma("unroll")                                                          \
            for (int c = 0; c < 4; c++) acc[a][bq][c] = 0.f;                           \
    int KT = (KWv) >> 4;                                                               \
    _Pragma("unroll")                                                                  \
    for (int i = tid; i < 512; i += 128) {                                             \
        int m = i >> 2, u = i & 3;                                                     \
        uint32_t sw = (uint32_t)(m * 64 + ((u ^ ((m >> 1) & 3)) * 16));                \
        cpasync16(sbA + sw, in + (m0 + m) * (size_t)(KWv) + 4 * u);                    \
        cpasync16(sbB + sw, W + (size_t)(n0 + m) * (KWv) + 4 * u);                     \
    }                                                                                  \
    asm volatile("cp.async.commit_group;\n" ::);                                       \
    for (int kt = 0; kt < KT; kt++) {                                                  \
        int cur = kt & 1;                                                              \
        if (kt + 1 < KT) {                                                             \
            int kw0 = (kt + 1) * 16;                                                   \
            int nxt = cur ^ 1;                                                         \
            _Pragma("unroll")                                                          \
            for (int i = tid; i < 512; i += 128) {                                     \
                int m = i >> 2, u = i & 3;                                             \
                uint32_t sw = (uint32_t)(m * 64 + ((u ^ ((m >> 1) & 3)) * 16));        \
                cpasync16(sbA + nxt * 8192 + sw,                                       \
                          in + (m0 + m) * (size_t)(KWv) + kw0 + 4 * u);                \
                cpasync16(sbB + nxt * 8192 + sw,                                       \
                          W + (size_t)(n0 + m) * (KWv) + kw0 + 4 * u);                 \
            }                                                                          \
            asm volatile("cp.async.commit_group;\n" ::);                               \
            asm volatile("cp.async.wait_group 1;\n" ::);                               \
        } else {                                                                       \
            asm volatile("cp.async.wait_group 0;\n" ::);                               \
        }                                                                              \
        __syncthreads();                                                               \
        uint32_t Ab = sbA + cur * 8192;                                                \
        uint32_t Bb = sbB + cur * 8192;                                                \
        _Pragma("unroll")                                                              \
        for (int s = 0; s < 2; s++) {                                                  \
            uint32_t afr[4][4], bfr[4][4];                                             \
            _Pragma("unroll")                                                          \
            for (int mt = 0; mt < 4; mt++) ldsm4(afr[mt], Ab + aoff[s] + mt * 1024);   \
            _Pragma("unroll")                                                          \
            for (int pq = 0; pq < 4; pq++) ldsm4(bfr[pq], Bb + boff[s] + pq * 1024);   \
            _Pragma("unroll")                                                          \
            for (int mt = 0; mt < 4; mt++)                                             \
                _Pragma("unroll")                                                      \
                for (int pq = 0; pq < 4; pq++) {                                       \
                    mma_f16(acc[mt][2 * pq],     afr[mt], bfr[pq][0], bfr[pq][1]);     \
                    mma_f16(acc[mt][2 * pq + 1], afr[mt], bfr[pq][2], bfr[pq][3]);     \
                }                                                                      \
        }                                                                              \
        __syncthreads();                                                               \
    }

__global__ void __launch_bounds__(128, 2)
k_gemm(const uint32_t* __restrict__ in, const uint32_t* __restrict__ W,
       const float* __restrict__ bias, uint32_t* __restrict__ out16,
       float* __restrict__ out32, int KW, int NoW, int relu, int ldout32) {
    __shared__ SmemU su;
    __shared__ float bias_s[128];

    int n0 = blockIdx.x * 128;
    size_t m0 = (size_t)blockIdx.y * 128;
    int tid = threadIdx.x;
    int wrp = tid >> 5, lane = tid & 31;
    int gid = lane >> 2, ctid = lane & 3;
    int warp_m = (wrp & 1) * 64;
    int warp_n = (wrp >> 1) * 64;

    bias_s[tid] = bias[n0 + tid];

    GEMM_PRO_MAIN(KW)

    if (out16) {
#pragma unroll
        for (int mt = 0; mt < 4; mt++) {
            int m = warp_m + mt * 16 + gid;
#pragma unroll
            for (int nt = 0; nt < 8; nt++) {
                int j = warp_n + nt * 8 + 2 * ctid;
                float v0 = fmaxf(acc[mt][nt][0] + bias_s[j], 0.f);
                float v1 = fmaxf(acc[mt][nt][1] + bias_s[j + 1], 0.f);
                float v2 = fmaxf(acc[mt][nt][2] + bias_s[j], 0.f);
                float v3 = fmaxf(acc[mt][nt][3] + bias_s[j + 1], 0.f);
                int wc = (j >> 1);
                su.stage[m * 68 + wc]       = packh2(v0, v1);
                su.stage[(m + 8) * 68 + wc] = packh2(v2, v3);
            }
        }
        __syncthreads();
        int wbase = n0 >> 1;
#pragma unroll
        for (int idx = tid; idx < 128 * 16; idx += 128) {
            int r = idx >> 4, q = idx & 15;
            uint4 v = *(uint4*)&su.stage[r * 68 + q * 4];
            *(uint4*)&out16[(m0 + r) * (size_t)NoW + wbase + q * 4] = v;
        }
    } else {
#pragma unroll
        for (int mt = 0; mt < 4; mt++) {
            size_t m = m0 + (size_t)(warp_m + mt * 16 + gid);
#pragma unroll
            for (int nt = 0; nt < 8; nt++) {
                int j = warp_n + nt * 8 + 2 * ctid;
                float v0 = acc[mt][nt][0] + bias_s[j];
                float v1 = acc[mt][nt][1] + bias_s[j + 1];
                float v2 = acc[mt][nt][2] + bias_s[j];
                float v3 = acc[mt][nt][3] + bias_s[j + 1];
                if (relu) {
                    v0 = fmaxf(v0, 0.f); v1 = fmaxf(v1, 0.f);
                    v2 = fmaxf(v2, 0.f); v3 = fmaxf(v3, 0.f);
                }
                *(float2*)&out32[m * ldout32 + n0 + j] = make_float2(v0, v1);
                *(float2*)&out32[(m + 8) * ldout32 + n0 + j] = make_float2(v2, v3);
            }
        }
    }
}

// pixel GEMM with fused cell-add + relu epilogue -> act1 [4*PROWS][512w]
__global__ void __launch_bounds__(128, 2)
k_gemm_fused(const uint32_t* __restrict__ in, const uint32_t* __restrict__ W,
             const float* __restrict__ C, const int* __restrict__ idx4,
             uint32_t* __restrict__ out16) {
    __shared__ SmemU su;

    int n0 = blockIdx.x * 128;
    size_t m0 = (size_t)blockIdx.y * 128;
    int tid = threadIdx.x;
    int wrp = tid >> 5, lane = tid & 31;
    int gid = lane >> 2, ctid = lane & 3;
    int warp_m = (wrp & 1) * 64;
    int warp_n = (wrp >> 1) * 64;

    GEMM_PRO_MAIN(80)

#pragma unroll 1
    for (int s = 0; s < 4; s++) {
#pragma unroll
        for (int mt = 0; mt < 4; mt++) {
            int mrow = warp_m + mt * 16 + gid;
            int i0 = idx4[(m0 + mrow) * 4 + s];
            int i1 = idx4[(m0 + mrow + 8) * 4 + s];
            const float* C0 = C + (size_t)i0 * 1024 + n0;
            const float* C1 = C + (size_t)i1 * 1024 + n0;
#pragma unroll
            for (int nt = 0; nt < 8; nt++) {
                int j = warp_n + nt * 8 + 2 * ctid;
                float2 c0 = *(const float2*)&C0[j];
                float2 c1 = *(const float2*)&C1[j];
                float v0 = fmaxf(acc[mt][nt][0] + c0.x, 0.f);
                float v1 = fmaxf(acc[mt][nt][1] + c0.y, 0.f);
                float v2 = fmaxf(acc[mt][nt][2] + c1.x, 0.f);
                float v3 = fmaxf(acc[mt][nt][3] + c1.y, 0.f);
                int wc = (j >> 1);
                su.stage[mrow * 68 + wc]       = packh2(v0, v1);
                su.stage[(mrow + 8) * 68 + wc] = packh2(v2, v3);
            }
        }
        __syncthreads();
        size_t rowbase = (size_t)s * PROWS + m0;
        int wbase = n0 >> 1;
#pragma unroll
        for (int idx = tid; idx < 128 * 16; idx += 128) {
            int r = idx >> 4, q = idx & 15;
            uint4 v = *(uint4*)&su.stage[r * 68 + q * 4];
            *(uint4*)&out16[(rowbase + r) * 512 + wbase + q * 4] = v;
        }
        __syncthreads();
    }
}

// ---------------- layer 5 + softmax combine (act4 fp32 row-major [M][128]) ----------------
__global__ void k_combine(const float* __restrict__ act,
                          const float* __restrict__ w5, const float* __restrict__ b5,
                          float* __restrict__ out) {
    __shared__ float2 ws[128];
    int tid = threadIdx.x;
    if (tid < 128) ws[tid] = make_float2(w5[2 * tid], w5[2 * tid + 1]);
    __syncthreads();

    int wid = tid >> 5, lane = tid & 31;
    int pg = blockIdx.x * 8 + wid;
    int b = pg >> 16, n = pg & 65535;

    float p0[4], p1[4];
#pragma unroll
    for (int s = 0; s < 4; s++) {
        size_t r = ((size_t)(s * BATCH + b) << 16) + (size_t)n;
        const float* row = act + r * 128;
        float4 v = *(const float4*)&row[lane * 4];
        float2 w0 = ws[4 * lane], w1 = ws[4 * lane + 1];
        float2 w2 = ws[4 * lane + 2], w3 = ws[4 * lane + 3];
        float a0 = v.x * w0.x + v.y * w1.x + v.z * w2.x + v.w * w3.x;
        float a1 = v.x * w0.y + v.y * w1.y + v.z * w2.y + v.w * w3.y;
#pragma unroll
        for (int o = 16; o > 0; o >>= 1) {
            a0 += __shfl_xor_sync(0xFFFFFFFF, a0, o);
            a1 += __shfl_xor_sync(0xFFFFFFFF, a1, o);
        }
        p0[s] = a0 + b5[0];
        p1[s] = a1 + b5[1];
    }
    if (lane == 0) {
        float mx = fmaxf(fmaxf(p1[0], p1[1]), fmaxf(p1[2], p1[3]));
        float e0 = expf(p1[0] - mx), e1 = expf(p1[1] - mx);
        float e2 = expf(p1[2] - mx), e3 = expf(p1[3] - mx);
        float sum = e0 + e1 + e2 + e3;
        out[(size_t)b * NPIX + n] = (p0[0] * e0 + p0[1] * e1 + p0[2] * e2 + p0[3] * e3) / sum;
    }
}

// ---------------- launch ----------------
extern "C" void kernel_launch(void* const* d_in, const int* in_sizes, int n_in,
                              void* d_out, int out_size) {
    const float* feat  = (const float*)d_in[0];
    const float* coord = (const float*)d_in[1];
    const float* hr    = (const float*)d_in[2];
    const float* lr    = (const float*)d_in[3];
    const float* w1 = (const float*)d_in[4];
    const float* b1 = (const float*)d_in[5];
    const float* w2 = (const float*)d_in[6];
    const float* b2 = (const float*)d_in[7];
    const float* w3 = (const float*)d_in[8];
    const float* b3 = (const float*)d_in[9];
    const float* w4 = (const float*)d_in[10];
    const float* b4 = (const float*)d_in[11];
    const float* w5 = (const float*)d_in[12];
    const float* b5 = (const float*)d_in[13];

    uint32_t *A, *B1, *Gp, *Gc, *Wb;
    float* C;
    int* idx4;
    cudaGetSymbolAddress((void**)&A,   g_A);
    cudaGetSymbolAddress((void**)&B1,  g_B1);
    cudaGetSymbolAddress((void**)&Gp,  g_Gp);
    cudaGetSymbolAddress((void**)&Gc,  g_Gc);
    cudaGetSymbolAddress((void**)&C,   g_C);
    cudaGetSymbolAddress((void**)&idx4, g_idx);
    cudaGetSymbolAddress((void**)&Wb,  g_W);

    uint32_t* W2 = Wb;                        // [512][512w]
    uint32_t* W3 = W2 + 512 * 512;            // [256][256w]
    uint32_t* W4 = W3 + 256 * 256;            // [128][128w]
    uint32_t* Wg = W4 + 128 * 128;            // [1024][80w]
    uint32_t* Wc = Wg + 1024 * 80;            // [1024][144w]

    k_prep<<<(512 * 512 + 255) / 256, 256>>>(w2, W2, 1024, 512, 512);
    k_prep<<<(256 * 256 + 255) / 256, 256>>>(w3, W3, 512, 256, 256);
    k_prep<<<(128 * 128 + 255) / 256, 256>>>(w4, W4, 256, 128, 128);
    k_prepWg<<<(1024 * 80 + 255) / 256, 256>>>(w1, Wg);
    k_prepWc<<<(1024 * 144 + 255) / 256, 256>>>(w1, Wc);

    k_buildGp<<<PROWS / 32, 256>>>(hr, coord, Gp, idx4);
    k_buildGc<<<(8320 * 144 + 255) / 256, 256>>>(feat, lr, Gc);

    // cell table: C[8320][1024] fp32 = Gc * Wc^T + b1 (no relu)
    k_gemm<<<dim3(8, 65), 128>>>(Gc, Wc, b1, nullptr, C, 144, 0, 0, 1024);
    // pixel GEMM fused: act1[4*PROWS][512w] = relu(Gp*Wg^T + C[idx4])
    k_gemm_fused<<<dim3(8, PROWS / 128), 128>>>(Gp, Wg, C, idx4, A);
    // L2: act1 -> act2[M][256w] in B1
    k_gemm<<<dim3(4, 4096), 128>>>(A, W2, b2, B1, nullptr, 512, 256, 1, 0);
    // L3: act2 -> act3[M][128w] in A
    k_gemm<<<dim3(2, 4096), 128>>>(B1, W3, b3, A, nullptr, 256, 128, 1, 0);
    // L4: act3 -> act4 fp32 [M][128] in B1
    k_gemm<<<dim3(1, 4096), 128>>>(A, W4, b4, nullptr, (float*)B1, 128, 0, 1, 128);

    k_combine<<<BATCH * NPIX / 8, 256>>>((const float*)B1, w5, b5, (float*)d_out);
}

// round 10
// speedup vs baseline: 1.5462x; 1.0381x over previous
#include <cuda_runtime.h>
#include <cuda_fp16.h>
#include <cstdint>

// Problem constants
#define NPIX   65536
#define BATCH  2
#define MROWS  524288
#define PROWS  131072       // B * NPIX (pixel-GEMM rows)

// Static scratch. Row-major packed half2. Activation row order: pixel*4 + shift.
__device__ uint32_t g_A[512u * 524288u];    // act1 [M][512w] / act3 [M][128w]
__device__ uint32_t g_B1[256u * 524288u];   // act2 [M][256w]
__device__ uint32_t g_Gp[131072u * 80u];    // pixel-GEMM input [PROWS][80w]
__device__ uint32_t g_Gc[8320u * 144u];     // cell-GEMM input [8320][144w]
__device__ float    g_C[8320u * 1024u];     // cell table fp32 [8320][1024]
__device__ int      g_idx[131072u * 4u];    // per-(pixel,shift) cell row
__device__ uint32_t g_W[600000];            // packed fp16 weights

// ---------------- helpers ----------------
__device__ __forceinline__ void mma_f16(float c[4], const uint32_t a[4],
                                        uint32_t b0, uint32_t b1) {
    asm volatile(
        "mma.sync.aligned.m16n8k16.row.col.f32.f16.f16.f32 "
        "{%0,%1,%2,%3}, {%4,%5,%6,%7}, {%8,%9}, {%0,%1,%2,%3};\n"
        : "+f"(c[0]), "+f"(c[1]), "+f"(c[2]), "+f"(c[3])
        : "r"(a[0]), "r"(a[1]), "r"(a[2]), "r"(a[3]), "r"(b0), "r"(b1));
}
__device__ __forceinline__ void ldsm4(uint32_t r[4], uint32_t addr) {
    asm volatile("ldmatrix.sync.aligned.m8n8.x4.shared.b16 {%0,%1,%2,%3}, [%4];"
                 : "=r"(r[0]), "=r"(r[1]), "=r"(r[2]), "=r"(r[3]) : "r"(addr));
}
__device__ __forceinline__ uint32_t s2u(const void* p) {
    uint32_t a;
    asm("{ .reg .u64 t; cvta.to.shared.u64 t, %1; cvt.u32.u64 %0, t; }" : "=r"(a) : "l"(p));
    return a;
}
__device__ __forceinline__ void cpasync16(uint32_t smem, const void* gmem) {
    asm volatile("cp.async.cg.shared.global [%0], [%1], 16;\n" :: "r"(smem), "l"(gmem));
}
__device__ __forceinline__ uint32_t packh2(float a, float b) {
    __half2 h = __floats2half2_rn(a, b);
    return *(uint32_t*)&h;
}

// ---------------- weight preps ----------------
__global__ void k_prep(const float* __restrict__ w, uint32_t* __restrict__ dst,
                       int Ksrc, int KW, int No) {
    int i = blockIdx.x * 256 + threadIdx.x;
    if (i >= KW * No) return;
    int j = i / KW;
    int kk = i - j * KW;
    int k0 = 2 * kk, k1 = 2 * kk + 1;
    float v0 = (k0 < Ksrc) ? w[(size_t)k0 * No + j] : 0.f;
    float v1 = (k1 < Ksrc) ? w[(size_t)k1 * No + j] : 0.f;
    dst[(size_t)j * KW + kk] = packh2(v0, v1);
}
__global__ void k_prepWg(const float* __restrict__ w1, uint32_t* __restrict__ dst) {
    int i = blockIdx.x * 256 + threadIdx.x;
    if (i >= 1024 * 80) return;
    int j = i / 80, kk = i - j * 80;
    float v0 = 0.f, v1 = 0.f;
    if (kk < 64) {
        int c = 2 * kk;
        v0 = w1[(size_t)(128 + c) * 1024 + j] + w1[(size_t)(256 + c) * 1024 + j];
        v1 = w1[(size_t)(129 + c) * 1024 + j] + w1[(size_t)(257 + c) * 1024 + j];
    } else if (kk == 64) {
        v0 = w1[(size_t)384 * 1024 + j];
        v1 = w1[(size_t)385 * 1024 + j];
    }
    dst[(size_t)j * 80 + kk] = packh2(v0, v1);
}
__global__ void k_prepWc(const float* __restrict__ w1, uint32_t* __restrict__ dst) {
    int i = blockIdx.x * 256 + threadIdx.x;
    if (i >= 1024 * 144) return;
    int j = i / 144, kk = i - j * 144;
    float v0 = 0.f, v1 = 0.f;
    if (kk < 64) {
        int c = 2 * kk;
        v0 = w1[(size_t)c * 1024 + j];
        v1 = w1[(size_t)(c + 1) * 1024 + j];
    } else if (kk < 128) {
        int c = 2 * (kk - 64);
        v0 = -w1[(size_t)(256 + c) * 1024 + j];
        v1 = -w1[(size_t)(257 + c) * 1024 + j];
    } else if (kk == 128) {
        v0 = w1[(size_t)384 * 1024 + j];
        v1 = w1[(size_t)385 * 1024 + j];
    }
    dst[(size_t)j * 144 + kk] = packh2(v0, v1);
}

// ---------------- build pixel input Gp [PROWS][80w] + idx4 ----------------
__global__ void k_buildGp(const float* __restrict__ hr, const float* __restrict__ coord,
                          uint32_t* __restrict__ Gp, int* __restrict__ idx4) {
    __shared__ uint32_t sm[32][80];
    __shared__ int s_hi[32];
    __shared__ float s_fH[32];
    __shared__ uint32_t s_cw[32];

    int tid = threadIdx.x;
    if (tid < 32) {
        int gp = blockIdx.x * 32 + tid;
        int b = gp >> 16, n = gp & 65535;
        float gy = coord[((size_t)b * NPIX + n) * 2 + 0];
        float gx = coord[((size_t)b * NPIX + n) * 2 + 1];
        int iyH = (int)floorf((gy + 1.f) * 128.f);
        int ixH = (int)floorf((gx + 1.f) * 128.f);
        bool vH = (iyH >= 0) && (iyH < 256) && (ixH >= 0) && (ixH < 256);
        int iyHc = min(max(iyH, 0), 255), ixHc = min(max(ixH, 0), 255);
        s_hi[tid] = iyHc * 256 + ixHc;
        s_fH[tid] = vH ? 1.f : 0.f;
        s_cw[tid] = packh2(gy * 64.f, gx * 64.f);
#pragma unroll
        for (int s = 0; s < 4; s++) {
            float vx = (s & 2) ? 1.f : -1.f;
            float vy = (s & 1) ? 1.f : -1.f;
            float cy = gy + vx * (1.f / 64.f);
            float cx = gx + vy * (1.f / 64.f);
            int iyL = (int)floorf((cy + 1.f) * 32.f);
            int ixL = (int)floorf((cx + 1.f) * 32.f);
            bool vL = (iyL >= 0) && (iyL < 64) && (ixL >= 0) && (ixL < 64);
            idx4[(size_t)gp * 4 + s] = vL ? (b * 4096 + iyL * 64 + ixL) : 8192;
        }
    }
    __syncthreads();

    int p = tid >> 3, t = tid & 7;
    {
        int gp = blockIdx.x * 32 + p;
        int b = gp >> 16;
        float fH = s_fH[p];
        size_t hrb = ((size_t)b * 128) * 65536 + s_hi[p];
        for (int w = t; w < 80; w += 8) {
            uint32_t v;
            if (w < 64) {
                int c = 2 * w;
                v = packh2(fH * hr[hrb + (size_t)c * 65536],
                           fH * hr[hrb + (size_t)(c + 1) * 65536]);
            } else if (w == 64) {
                v = s_cw[p];
            } else {
                v = 0u;
            }
            sm[p][w] = v;
        }
    }
    __syncthreads();

    size_t r0 = (size_t)blockIdx.x * 32;
    for (int idx = tid; idx < 32 * 20; idx += 256) {
        int r = idx / 20, q = idx - r * 20;
        uint4 v = *(uint4*)&sm[r][q * 4];
        *(uint4*)&Gp[(r0 + r) * 80 + q * 4] = v;
    }
}

// ---------------- build cell input Gc [8320][144w] ----------------
__global__ void k_buildGc(const float* __restrict__ feat, const float* __restrict__ lr,
                          uint32_t* __restrict__ Gc) {
    int i = blockIdx.x * 256 + threadIdx.x;
    if (i >= 8320 * 144) return;
    int row = i / 144, w = i - row * 144;
    uint32_t v = 0u;
    if (row < 8192) {
        int b = row >> 12, cell = row & 4095;
        int iy = cell >> 6, ix = cell & 63;
        size_t li = (size_t)b * 128 * 4096 + iy * 64 + ix;
        if (w < 64) {
            int c = 2 * w;
            v = packh2(feat[li + (size_t)c * 4096], feat[li + (size_t)(c + 1) * 4096]);
        } else if (w < 128) {
            int c = 2 * (w - 64);
            v = packh2(lr[li + (size_t)c * 4096], lr[li + (size_t)(c + 1) * 4096]);
        } else if (w == 128) {
            v = packh2((float)(63 - 2 * iy), (float)(63 - 2 * ix));
        }
    }
    Gc[(size_t)row * 144 + w] = v;
}

// ---------------- fp16 GEMM core: 3-stage cp.async, 1 sync/chunk ----------------
// Dynamic smem: pipeline 3 x (A 8KB + B 8KB) = 48KB; epilogue reuses the region.
#define GEMM_MAIN(KWv)                                                                  \
    uint32_t sb = s2u(dynsm);                                                           \
    int mA = warp_m + (lane & 7) + (lane & 8);                                          \
    int uA = (lane >> 4) & 1;                                                           \
    int nB = warp_n + (lane & 7) + ((lane >> 4) << 3);                                  \
    int uB = (lane >> 3) & 1;                                                           \
    uint32_t aoff[2], boff[2];                                                          \
    _Pragma("unroll")                                                                   \
    for (int s = 0; s < 2; s++) {                                                       \
        aoff[s] = (uint32_t)(mA * 64 + (((2 * s + uA) ^ ((mA >> 1) & 3)) * 16));        \
        boff[s] = (uint32_t)(nB * 64 + (((2 * s + uB) ^ ((nB >> 1) & 3)) * 16));        \
    }                                                                                   \
    float acc[4][8][4];                                                                 \
    _Pragma("unroll")                                                                   \
    for (int a = 0; a < 4; a++)                                                         \
        _Pragma("unroll")                                                               \
        for (int bq = 0; bq < 8; bq++)                                                  \
            _Pragma("unroll")                                                           \
            for (int c = 0; c < 4; c++) acc[a][bq][c] = 0.f;                            \
    auto load_st = [&](int st, int kw0) {                                               \
        _Pragma("unroll")                                                               \
        for (int i = tid; i < 512; i += 128) {                                          \
            int m = i >> 2, u = i & 3;                                                  \
            uint32_t sw = (uint32_t)(m * 64 + ((u ^ ((m >> 1) & 3)) * 16));             \
            cpasync16(sb + st * 16384 + sw,                                             \
                      in + (m0 + m) * (size_t)(KWv) + kw0 + 4 * u);                     \
            cpasync16(sb + st * 16384 + 8192 + sw,                                      \
                      W + (size_t)(n0 + m) * (KWv) + kw0 + 4 * u);                      \
        }                                                                               \
        asm volatile("cp.async.commit_group;\n" ::);                                    \
    };                                                                                  \
    int KT = (KWv) >> 4;                                                                \
    load_st(0, 0);                                                                      \
    load_st(1, 16);                                                                     \
    int stc = 0;                                                                        \
    for (int kt = 0; kt < KT; kt++) {                                                   \
        if (kt == KT - 1) { asm volatile("cp.async.wait_group 0;\n" ::); }              \
        else              { asm volatile("cp.async.wait_group 1;\n" ::); }              \
        __syncthreads();                                                                \
        if (kt + 2 < KT) {                                                              \
            int stn = stc + 2; if (stn >= 3) stn -= 3;                                  \
            load_st(stn, (kt + 2) * 16);                                                \
        }                                                                               \
        uint32_t Ab = sb + stc * 16384;                                                 \
        uint32_t Bb = Ab + 8192;                                                        \
        _Pragma("unroll")                                                               \
        for (int s = 0; s < 2; s++) {                                                   \
            uint32_t afr[4][4], bfr[4][4];                                              \
            _Pragma("unroll")                                                           \
            for (int mt = 0; mt < 4; mt++) ldsm4(afr[mt], Ab + aoff[s] + mt * 1024);    \
            _Pragma("unroll")                                                           \
            for (int pq = 0; pq < 4; pq++) ldsm4(bfr[pq], Bb + boff[s] + pq * 1024);    \
            _Pragma("unroll")                                                           \
            for (int mt = 0; mt < 4; mt++)                                              \
                _Pragma("unroll")                                                       \
                for (int pq = 0; pq < 4; pq++) {                                        \
                    mma_f16(acc[mt][2 * pq],     afr[mt], bfr[pq][0], bfr[pq][1]);      \
                    mma_f16(acc[mt][2 * pq + 1], afr[mt], bfr[pq][2], bfr[pq][3]);      \
                }                                                                       \
        }                                                                               \
        stc = (stc == 2) ? 0 : stc + 1;                                                 \
    }                                                                                   \
    __syncthreads();

// generic GEMM (L2, L3, cell table)
__global__ void __launch_bounds__(128, 2)
k_gemm(const uint32_t* __restrict__ in, const uint32_t* __restrict__ W,
       const float* __restrict__ bias, uint32_t* __restrict__ out16,
       float* __restrict__ out32, int KW, int NoW, int relu, int ldout32) {
    extern __shared__ uint32_t dynsm[];
    __shared__ float bias_s[128];

    int n0 = blockIdx.x * 128;
    size_t m0 = (size_t)blockIdx.y * 128;
    int tid = threadIdx.x;
    int wrp = tid >> 5, lane = tid & 31;
    int gid = lane >> 2, ctid = lane & 3;
    int warp_m = (wrp & 1) * 64;
    int warp_n = (wrp >> 1) * 64;

    bias_s[tid] = bias[n0 + tid];

    GEMM_MAIN(KW)

    if (out16) {
        uint32_t* stg = dynsm;
#pragma unroll
        for (int mt = 0; mt < 4; mt++) {
            int m = warp_m + mt * 16 + gid;
#pragma unroll
            for (int nt = 0; nt < 8; nt++) {
                int j = warp_n + nt * 8 + 2 * ctid;
                float v0 = fmaxf(acc[mt][nt][0] + bias_s[j], 0.f);
                float v1 = fmaxf(acc[mt][nt][1] + bias_s[j + 1], 0.f);
                float v2 = fmaxf(acc[mt][nt][2] + bias_s[j], 0.f);
                float v3 = fmaxf(acc[mt][nt][3] + bias_s[j + 1], 0.f);
                int wc = (j >> 1);
                stg[m * 68 + wc]       = packh2(v0, v1);
                stg[(m + 8) * 68 + wc] = packh2(v2, v3);
            }
        }
        __syncthreads();
        int wbase = n0 >> 1;
#pragma unroll
        for (int idx = tid; idx < 128 * 16; idx += 128) {
            int r = idx >> 4, q = idx & 15;
            uint4 v = *(uint4*)&stg[r * 68 + q * 4];
            *(uint4*)&out16[(m0 + r) * (size_t)NoW + wbase + q * 4] = v;
        }
    } else {
#pragma unroll
        for (int mt = 0; mt < 4; mt++) {
            size_t m = m0 + (size_t)(warp_m + mt * 16 + gid);
#pragma unroll
            for (int nt = 0; nt < 8; nt++) {
                int j = warp_n + nt * 8 + 2 * ctid;
                float v0 = acc[mt][nt][0] + bias_s[j];
                float v1 = acc[mt][nt][1] + bias_s[j + 1];
                float v2 = acc[mt][nt][2] + bias_s[j];
                float v3 = acc[mt][nt][3] + bias_s[j + 1];
                if (relu) {
                    v0 = fmaxf(v0, 0.f); v1 = fmaxf(v1, 0.f);
                    v2 = fmaxf(v2, 0.f); v3 = fmaxf(v3, 0.f);
                }
                *(float2*)&out32[m * ldout32 + n0 + j] = make_float2(v0, v1);
                *(float2*)&out32[(m + 8) * ldout32 + n0 + j] = make_float2(v2, v3);
            }
        }
    }
}

// pixel GEMM, fused cell-add + relu; writes act1 rows interleaved (pixel*4+shift)
__global__ void __launch_bounds__(128, 2)
k_gemm_fused(const uint32_t* __restrict__ in, const uint32_t* __restrict__ W,
             const float* __restrict__ C, const int* __restrict__ idx4,
             uint32_t* __restrict__ out16) {
    extern __shared__ uint32_t dynsm[];

    int n0 = blockIdx.x * 128;
    size_t m0 = (size_t)blockIdx.y * 128;   // pixel base
    int tid = threadIdx.x;
    int wrp = tid >> 5, lane = tid & 31;
    int gid = lane >> 2, ctid = lane & 3;
    int warp_m = (wrp & 1) * 64;
    int warp_n = (wrp >> 1) * 64;

    GEMM_MAIN(80)

    uint32_t* stg = dynsm;
#pragma unroll 1
    for (int s = 0; s < 4; s++) {
#pragma unroll
        for (int mt = 0; mt < 4; mt++) {
            int mrow = warp_m + mt * 16 + gid;
            int i0 = idx4[(m0 + mrow) * 4 + s];
            int i1 = idx4[(m0 + mrow + 8) * 4 + s];
            const float* C0 = C + (size_t)i0 * 1024 + n0;
            const float* C1 = C + (size_t)i1 * 1024 + n0;
#pragma unroll
            for (int nt = 0; nt < 8; nt++) {
                int j = warp_n + nt * 8 + 2 * ctid;
                float2 c0 = *(const float2*)&C0[j];
                float2 c1 = *(const float2*)&C1[j];
                float v0 = fmaxf(acc[mt][nt][0] + c0.x, 0.f);
                float v1 = fmaxf(acc[mt][nt][1] + c0.y, 0.f);
                float v2 = fmaxf(acc[mt][nt][2] + c1.x, 0.f);
                float v3 = fmaxf(acc[mt][nt][3] + c1.y, 0.f);
                int wc = (j >> 1);
                stg[mrow * 68 + wc]       = packh2(v0, v1);
                stg[(mrow + 8) * 68 + wc] = packh2(v2, v3);
            }
        }
        __syncthreads();
        int wbase = n0 >> 1;
#pragma unroll
        for (int idx = tid; idx < 128 * 16; idx += 128) {
            int r = idx >> 4, q = idx & 15;
            uint4 v = *(uint4*)&stg[r * 68 + q * 4];
            *(uint4*)&out16[((m0 + r) * 4 + (size_t)s) * 512 + wbase + q * 4] = v;
        }
        __syncthreads();
    }
}

// L4 + L5 + softmax fused: reads act3 [M][128w] (rows pixel*4+shift), writes d_out
__global__ void __launch_bounds__(128, 2)
k_gemm45(const uint32_t* __restrict__ in, const uint32_t* __restrict__ W,
         const float* __restrict__ b4, const float* __restrict__ w5,
         const float* __restrict__ b5, float* __restrict__ out) {
    extern __shared__ uint32_t dynsm[];
    __shared__ float bias_s[128];
    __shared__ float2 w5s[128];

    int n0 = 0;
    size_t m0 = (size_t)blockIdx.y * 128;
    int tid = threadIdx.x;
    int wrp = tid >> 5, lane = tid & 31;
    int gid = lane >> 2, ctid = lane & 3;
    int warp_m = (wrp & 1) * 64;
    int warp_n = (wrp >> 1) * 64;

    bias_s[tid] = b4[tid];
    w5s[tid] = make_float2(w5[2 * tid], w5[2 * tid + 1]);

    GEMM_MAIN(128)

    // stage act4 tile fp32 [128][136]
    float* stgf = (float*)dynsm;
#pragma unroll
    for (int mt = 0; mt < 4; mt++) {
        int m = warp_m + mt * 16 + gid;
#pragma unroll
        for (int nt = 0; nt < 8; nt++) {
            int j = warp_n + nt * 8 + 2 * ctid;
            stgf[m * 136 + j]           = fmaxf(acc[mt][nt][0] + bias_s[j], 0.f);
            stgf[m * 136 + j + 1]       = fmaxf(acc[mt][nt][1] + bias_s[j + 1], 0.f);
            stgf[(m + 8) * 136 + j]     = fmaxf(acc[mt][nt][2] + bias_s[j], 0.f);
            stgf[(m + 8) * 136 + j + 1] = fmaxf(acc[mt][nt][3] + bias_s[j + 1], 0.f);
        }
    }
    __syncthreads();

    // per-thread row dot with w5 (row tid = pixel (m0+tid)/4, shift tid&3)
    const float* row = stgf + tid * 136;
    float d0 = 0.f, d1 = 0.f;
#pragma unroll
    for (int jj = 0; jj < 32; jj++) {
        float4 v = *(const float4*)&row[jj * 4];
        float2 wa = w5s[4 * jj], wb = w5s[4 * jj + 1];
        float2 wc = w5s[4 * jj + 2], wd = w5s[4 * jj + 3];
        d0 += v.x * wa.x + v.y * wb.x + v.z * wc.x + v.w * wd.x;
        d1 += v.x * wa.y + v.y * wb.y + v.z * wc.y + v.w * wd.y;
    }
    float p0 = d0 + b5[0];
    float p1 = d1 + b5[1];

    // softmax-combine across the 4 shifts (adjacent lanes)
    float o = fmaxf(p1, __shfl_xor_sync(0xFFFFFFFF, p1, 1));
    float mx = fmaxf(o, __shfl_xor_sync(0xFFFFFFFF, o, 2));
    float e = expf(p1 - mx);
    float num = p0 * e;
    float es = e + __shfl_xor_sync(0xFFFFFFFF, e, 1);
    es += __shfl_xor_sync(0xFFFFFFFF, es, 2);
    float ns = num + __shfl_xor_sync(0xFFFFFFFF, num, 1);
    ns += __shfl_xor_sync(0xFFFFFFFF, ns, 2);
    if ((tid & 3) == 0) out[(m0 >> 2) + (tid >> 2)] = ns / es;
}

// ---------------- launch ----------------
extern "C" void kernel_launch(void* const* d_in, const int* in_sizes, int n_in,
                              void* d_out, int out_size) {
    const float* feat  = (const float*)d_in[0];
    const float* coord = (const float*)d_in[1];
    const float* hr    = (const float*)d_in[2];
    const float* lr    = (const float*)d_in[3];
    const float* w1 = (const float*)d_in[4];
    const float* b1 = (const float*)d_in[5];
    const float* w2 = (const float*)d_in[6];
    const float* b2 = (const float*)d_in[7];
    const float* w3 = (const float*)d_in[8];
    const float* b3 = (const float*)d_in[9];
    const float* w4 = (const float*)d_in[10];
    const float* b4 = (const float*)d_in[11];
    const float* w5 = (const float*)d_in[12];
    const float* b5 = (const float*)d_in[13];

    uint32_t *A, *B1, *Gp, *Gc, *Wb;
    float* C;
    int* idx4;
    cudaGetSymbolAddress((void**)&A,   g_A);
    cudaGetSymbolAddress((void**)&B1,  g_B1);
    cudaGetSymbolAddress((void**)&Gp,  g_Gp);
    cudaGetSymbolAddress((void**)&Gc,  g_Gc);
    cudaGetSymbolAddress((void**)&C,   g_C);
    cudaGetSymbolAddress((void**)&idx4, g_idx);
    cudaGetSymbolAddress((void**)&Wb,  g_W);

    uint32_t* W2 = Wb;                        // [512][512w]
    uint32_t* W3 = W2 + 512 * 512;            // [256][256w]
    uint32_t* W4 = W3 + 256 * 256;            // [128][128w]
    uint32_t* Wg = W4 + 128 * 128;            // [1024][80w]
    uint32_t* Wc = Wg + 1024 * 80;            // [1024][144w]

    cudaFuncSetAttribute(k_gemm, cudaFuncAttributeMaxDynamicSharedMemorySize, 49152);
    cudaFuncSetAttribute(k_gemm_fused, cudaFuncAttributeMaxDynamicSharedMemorySize, 49152);
    cudaFuncSetAttribute(k_gemm45, cudaFuncAttributeMaxDynamicSharedMemorySize, 69632);

    k_prep<<<(512 * 512 + 255) / 256, 256>>>(w2, W2, 1024, 512, 512);
    k_prep<<<(256 * 256 + 255) / 256, 256>>>(w3, W3, 512, 256, 256);
    k_prep<<<(128 * 128 + 255) / 256, 256>>>(w4, W4, 256, 128, 128);
    k_prepWg<<<(1024 * 80 + 255) / 256, 256>>>(w1, Wg);
    k_prepWc<<<(1024 * 144 + 255) / 256, 256>>>(w1, Wc);

    k_buildGp<<<PROWS / 32, 256>>>(hr, coord, Gp, idx4);
    k_buildGc<<<(8320 * 144 + 255) / 256, 256>>>(feat, lr, Gc);

    // cell table: C[8320][1024] fp32 = Gc * Wc^T + b1 (no relu)
    k_gemm<<<dim3(8, 65), 128, 49152>>>(Gc, Wc, b1, nullptr, C, 144, 0, 0, 1024);
    // pixel GEMM fused -> act1 [M][512w], rows interleaved pixel*4+shift
    k_gemm_fused<<<dim3(8, PROWS / 128), 128, 49152>>>(Gp, Wg, C, idx4, A);
    // L2: act1 -> act2[M][256w] in B1
    k_gemm<<<dim3(4, 4096), 128, 49152>>>(A, W2, b2, B1, nullptr, 512, 256, 1, 0);
    // L3: act2 -> act3[M][128w] in A
    k_gemm<<<dim3(2, 4096), 128, 49152>>>(B1, W3, b3, A, nullptr, 256, 128, 1, 0);
    // L4 + L5 + softmax fused -> d_out
    k_gemm45<<<dim3(1, 4096), 128, 69632>>>(A, W4, b4, w5, b5, (float*)d_out);
}